// round 1
// baseline (speedup 1.0000x reference)
#include <cuda_runtime.h>
#include <cuda_bf16.h>

// Elementwise clip: out = min(max(x, lo), hi)
// x: [4194304, 8] fp32 = 33,554,432 elements (divisible by 4 -> clean float4 path)
// clamp_params: [1, 2] fp32 -> lo = p[0], hi = p[1]

__global__ __launch_bounds__(256) void clip_kernel_v4(
    const float4* __restrict__ x,
    const float* __restrict__ clamp_params,
    float4* __restrict__ out,
    int n4)
{
    int i = blockIdx.x * blockDim.x + threadIdx.x;
    if (i >= n4) return;

    const float lo = clamp_params[0];
    const float hi = clamp_params[1];

    float4 v = x[i];
    v.x = fminf(fmaxf(v.x, lo), hi);
    v.y = fminf(fmaxf(v.y, lo), hi);
    v.z = fminf(fmaxf(v.z, lo), hi);
    v.w = fminf(fmaxf(v.w, lo), hi);
    out[i] = v;
}

extern "C" void kernel_launch(void* const* d_in, const int* in_sizes, int n_in,
                              void* d_out, int out_size)
{
    const float* x = (const float*)d_in[0];
    const float* clamp_params = (const float*)d_in[1];
    float* out = (float*)d_out;

    int n = out_size;          // 33,554,432 elements
    int n4 = n >> 2;           // 8,388,608 float4s (n is divisible by 4)

    const int threads = 256;
    int blocks = (n4 + threads - 1) / threads;

    clip_kernel_v4<<<blocks, threads>>>(
        (const float4*)x, clamp_params, (float4*)out, n4);
}

// round 2
// speedup vs baseline: 1.0241x; 1.0241x over previous
#include <cuda_runtime.h>
#include <cuda_bf16.h>

// Elementwise clip: out = min(max(x, lo), hi)
// x: 33,554,432 fp32 = 8,388,608 float4s = 8192 blocks x 256 threads x 4 float4s (exact)
// Strategy: 4 front-batched 128-bit streaming loads per thread (MLP_p1=4),
// streaming stores (evict-first) since the 268MB sweep has zero L2 reuse.

#define VPT 4  // float4s per thread

__global__ __launch_bounds__(256) void clip_kernel_v4x4(
    const float4* __restrict__ x,
    const float* __restrict__ clamp_params,
    float4* __restrict__ out,
    int n4)
{
    const float lo = clamp_params[0];
    const float hi = clamp_params[1];

    int base = blockIdx.x * (256 * VPT) + threadIdx.x;

    float4 v[VPT];
    // Front-batched independent loads -> high per-warp MLP
    #pragma unroll
    for (int k = 0; k < VPT; k++) {
        int i = base + k * 256;
        if (i < n4) v[k] = __ldcs(&x[i]);
    }

    #pragma unroll
    for (int k = 0; k < VPT; k++) {
        v[k].x = fminf(fmaxf(v[k].x, lo), hi);
        v[k].y = fminf(fmaxf(v[k].y, lo), hi);
        v[k].z = fminf(fmaxf(v[k].z, lo), hi);
        v[k].w = fminf(fmaxf(v[k].w, lo), hi);
    }

    #pragma unroll
    for (int k = 0; k < VPT; k++) {
        int i = base + k * 256;
        if (i < n4) __stcs(&out[i], v[k]);
    }
}

extern "C" void kernel_launch(void* const* d_in, const int* in_sizes, int n_in,
                              void* d_out, int out_size)
{
    const float* x = (const float*)d_in[0];
    const float* clamp_params = (const float*)d_in[1];
    float* out = (float*)d_out;

    int n = out_size;          // 33,554,432
    int n4 = n >> 2;           // 8,388,608

    const int threads = 256;
    int blocks = (n4 + threads * VPT - 1) / (threads * VPT);  // 8192

    clip_kernel_v4x4<<<blocks, threads>>>(
        (const float4*)x, clamp_params, (float4*)out, n4);
}